// round 1
// baseline (speedup 1.0000x reference)
#include <cuda_runtime.h>

#define NQ 4
#define DIM 16

// Precomputed multilinear coefficient tensors T_w[81], duplicated (x=y) for f32x2.
__device__ float2 g_T[4 * 81];

// ---------------------------------------------------------------------------
// Precompute kernel: one block. Builds U (16x16 complex) from weights by
// simulating the circuit on identity columns (register-resident per lane),
// then M_w = Re(U^H D_w U), then T_w via the per-qubit (1,cos,sin) transform.
// ---------------------------------------------------------------------------
__global__ void precompute_T(const float* __restrict__ W, int n_layers) {
    __shared__ float Ur[DIM][DIM + 1], Ui[DIM][DIM + 1]; // [idx][col]
    __shared__ float Msh[4][DIM][DIM];

    const int t = threadIdx.x;

    if (t < DIM) {
        const int col = t;
        float ar[DIM], ai[DIM];
#pragma unroll
        for (int i = 0; i < DIM; i++) { ar[i] = (i == col) ? 1.f : 0.f; ai[i] = 0.f; }

        for (int l = 0; l < n_layers; l++) {
#pragma unroll
            for (int w = 0; w < NQ; w++) {
                const float* wp = &W[(l * NQ + w) * 3];
                float sx, cx, sy, cy, sz, cz;
                sincosf(0.5f * wp[0], &sx, &cx);
                sincosf(0.5f * wp[1], &sy, &cy);
                sincosf(0.5f * wp[2], &sz, &cz);
                const int mask = 1 << (NQ - 1 - w);
#pragma unroll
                for (int pi = 0; pi < DIM / 2; pi++) {
                    const int low = pi & (mask - 1);
                    const int i0 = ((pi - low) << 1) | low;
                    const int i1 = i0 | mask;
                    float a0r, a0i, a1r, a1i;
                    // RX
                    a0r = ar[i0]; a0i = ai[i0]; a1r = ar[i1]; a1i = ai[i1];
                    ar[i0] = cx * a0r + sx * a1i;  ai[i0] = cx * a0i - sx * a1r;
                    ar[i1] = sx * a0i + cx * a1r;  ai[i1] = -sx * a0r + cx * a1i;
                    // RY
                    a0r = ar[i0]; a0i = ai[i0]; a1r = ar[i1]; a1i = ai[i1];
                    ar[i0] = cy * a0r - sy * a1r;  ai[i0] = cy * a0i - sy * a1i;
                    ar[i1] = sy * a0r + cy * a1r;  ai[i1] = sy * a0i + cy * a1i;
                    // RZ
                    a0r = ar[i0]; a0i = ai[i0]; a1r = ar[i1]; a1i = ai[i1];
                    ar[i0] = cz * a0r + sz * a0i;  ai[i0] = cz * a0i - sz * a0r;
                    ar[i1] = cz * a1r - sz * a1i;  ai[i1] = cz * a1i + sz * a1r;
                }
            }
            // CNOT ring: new[idx] = old[perm[idx]]
#pragma unroll
            for (int w = 0; w < NQ; w++) {
                const int tq = (w + 1) & (NQ - 1);
                float nr[DIM], ni[DIM];
#pragma unroll
                for (int idx = 0; idx < DIM; idx++) {
                    const int src = ((idx >> (NQ - 1 - w)) & 1) ? (idx ^ (1 << (NQ - 1 - tq))) : idx;
                    nr[idx] = ar[src]; ni[idx] = ai[src];
                }
#pragma unroll
                for (int idx = 0; idx < DIM; idx++) { ar[idx] = nr[idx]; ai[idx] = ni[idx]; }
            }
        }
#pragma unroll
        for (int i = 0; i < DIM; i++) { Ur[i][col] = ar[i]; Ui[i][col] = ai[i]; }
    }
    __syncthreads();

    // M_w[i][j] = sum_idx z_w(idx) * (Ur[idx][i]Ur[idx][j] + Ui[idx][i]Ui[idx][j])
    for (int e = t; e < 4 * DIM * DIM; e += blockDim.x) {
        const int w = e >> 8, i = (e >> 4) & 15, j = e & 15;
        float acc = 0.f;
#pragma unroll
        for (int idx = 0; idx < DIM; idx++) {
            const float z = ((idx >> (NQ - 1 - w)) & 1) ? -1.f : 1.f;
            acc += z * (Ur[idx][i] * Ur[idx][j] + Ui[idx][i] * Ui[idx][j]);
        }
        Msh[w][i][j] = acc;
    }
    __syncthreads();

    // T_w[t0,t1,t2,t3]: per-qubit transform of paired index (i_q,j_q)->basis t:
    //   t=0 (const): p=00 coef .5, p=11 coef .5
    //   t=1 (cos)  : p=00 coef .5, p=11 coef -.5
    //   t=2 (sin)  : p=01 coef .5, p=10 coef .5
    for (int e = t; e < 4 * 81; e += blockDim.x) {
        const int w = e / 81, r = e % 81;
        const int tq[4] = { r / 27, (r / 9) % 3, (r / 3) % 3, r % 3 };
        const int   P[3][2]  = { {0, 3}, {0, 3}, {1, 2} };
        const float Cf[3][2] = { {0.5f, 0.5f}, {0.5f, -0.5f}, {0.5f, 0.5f} };
        float acc = 0.f;
        for (int a = 0; a < 2; a++)
        for (int b = 0; b < 2; b++)
        for (int c = 0; c < 2; c++)
        for (int d = 0; d < 2; d++) {
            const int p0 = P[tq[0]][a], p1 = P[tq[1]][b], p2 = P[tq[2]][c], p3 = P[tq[3]][d];
            const float co = Cf[tq[0]][a] * Cf[tq[1]][b] * Cf[tq[2]][c] * Cf[tq[3]][d];
            const int i = ((p0 >> 1) << 3) | ((p1 >> 1) << 2) | ((p2 >> 1) << 1) | (p3 >> 1);
            const int j = ((p0 & 1) << 3) | ((p1 & 1) << 2) | ((p2 & 1) << 1) | (p3 & 1);
            acc += co * Msh[w][i][j];
        }
        g_T[e] = make_float2(acc, acc);
    }
}

// ---------------------------------------------------------------------------
// Main kernel: 4 elements per thread, 2 packed f32x2 pairs.
// out_w(b) = <T_w, u0 x u1 x u2 x u3>, u_q = (1, cos x_q, sin x_q).
// ---------------------------------------------------------------------------
typedef unsigned long long u64;

__device__ __forceinline__ u64 pk2(float lo, float hi) {
    u64 r; asm("mov.b64 %0, {%1,%2};" : "=l"(r) : "f"(lo), "f"(hi)); return r;
}
__device__ __forceinline__ void upk2(u64 v, float& lo, float& hi) {
    asm("mov.b64 {%0,%1}, %2;" : "=f"(lo), "=f"(hi) : "l"(v));
}
__device__ __forceinline__ u64 fma2(u64 a, u64 b, u64 c) {
    u64 d; asm("fma.rn.f32x2 %0, %1, %2, %3;" : "=l"(d) : "l"(a), "l"(b), "l"(c)); return d;
}

__global__ __launch_bounds__(256)
void qlayer_main(const float4* __restrict__ x4, float4* __restrict__ out4, int B) {
    __shared__ u64 sT[4 * 81];
    for (int i = threadIdx.x; i < 4 * 81; i += blockDim.x) {
        float2 v = g_T[i];
        sT[i] = pk2(v.x, v.y);
    }
    __syncthreads();

    const int Q = (B + 3) >> 2;                    // elements per quarter
    const int tid = blockIdx.x * blockDim.x + threadIdx.x;
    if (tid >= Q) return;

    const int e0 = tid, e1 = tid + Q, e2 = tid + 2 * Q, e3 = tid + 3 * Q;
    const float4 z4 = make_float4(0.f, 0.f, 0.f, 0.f);
    const float4 xa = (e0 < B) ? x4[e0] : z4;
    const float4 xb = (e1 < B) ? x4[e1] : z4;
    const float4 xc = (e2 < B) ? x4[e2] : z4;
    const float4 xd = (e3 < B) ? x4[e3] : z4;

    // sincos of full angles, packed per pair: A=(e0,e1), B=(e2,e3)
    float ca[4], sa[4], cb[4], sb[4], cc[4], sc[4], cd[4], sd[4];
    const float* pa = &xa.x; const float* pb = &xb.x;
    const float* pc = &xc.x; const float* pd = &xd.x;
#pragma unroll
    for (int q = 0; q < 4; q++) {
        __sincosf(pa[q], &sa[q], &ca[q]);
        __sincosf(pb[q], &sb[q], &cb[q]);
        __sincosf(pc[q], &sc[q], &cc[q]);
        __sincosf(pd[q], &sd[q], &cd[q]);
    }
    u64 cA[4], sA[4], cB[4], sB[4];
#pragma unroll
    for (int q = 0; q < 4; q++) {
        cA[q] = pk2(ca[q], cb[q]); sA[q] = pk2(sa[q], sb[q]);
        cB[q] = pk2(cc[q], cd[q]); sB[q] = pk2(sc[q], sd[q]);
    }

    u64 outA[4], outB[4];
#pragma unroll
    for (int w = 0; w < 4; w++) {
        const u64* Tw = &sT[w * 81];
        u64 r0A[3], r0B[3];
#pragma unroll
        for (int t0 = 0; t0 < 3; t0++) {
            u64 r1A[3], r1B[3];
#pragma unroll
            for (int t1 = 0; t1 < 3; t1++) {
                u64 r2A[3], r2B[3];
#pragma unroll
                for (int t2 = 0; t2 < 3; t2++) {
                    const int base = ((t0 * 3 + t1) * 3 + t2) * 3;
                    const u64 T0 = Tw[base], T1 = Tw[base + 1], T2 = Tw[base + 2];
                    r2A[t2] = fma2(sA[3], T2, fma2(cA[3], T1, T0));
                    r2B[t2] = fma2(sB[3], T2, fma2(cB[3], T1, T0));
                }
                r1A[t1] = fma2(sA[2], r2A[2], fma2(cA[2], r2A[1], r2A[0]));
                r1B[t1] = fma2(sB[2], r2B[2], fma2(cB[2], r2B[1], r2B[0]));
            }
            r0A[t0] = fma2(sA[1], r1A[2], fma2(cA[1], r1A[1], r1A[0]));
            r0B[t0] = fma2(sB[1], r1B[2], fma2(cB[1], r1B[1], r1B[0]));
        }
        outA[w] = fma2(sA[0], r0A[2], fma2(cA[0], r0A[1], r0A[0]));
        outB[w] = fma2(sB[0], r0B[2], fma2(cB[0], r0B[1], r0B[0]));
    }

    float o0[4], o1[4], o2[4], o3[4];
#pragma unroll
    for (int w = 0; w < 4; w++) {
        upk2(outA[w], o0[w], o1[w]);
        upk2(outB[w], o2[w], o3[w]);
    }
    if (e0 < B) out4[e0] = make_float4(o0[0], o0[1], o0[2], o0[3]);
    if (e1 < B) out4[e1] = make_float4(o1[0], o1[1], o1[2], o1[3]);
    if (e2 < B) out4[e2] = make_float4(o2[0], o2[1], o2[2], o2[3]);
    if (e3 < B) out4[e3] = make_float4(o3[0], o3[1], o3[2], o3[3]);
}

extern "C" void kernel_launch(void* const* d_in, const int* in_sizes, int n_in,
                              void* d_out, int out_size) {
    const float* x = (const float*)d_in[0];
    const float* weights = (const float*)d_in[1];
    const int B = in_sizes[0] / 4;            // (B, 4) float32
    const int n_layers = in_sizes[1] / 12;    // (L, 4, 3) float32

    precompute_T<<<1, 256>>>(weights, n_layers);

    const int Q = (B + 3) / 4;                // threads (4 elements each)
    const int blocks = (Q + 255) / 256;
    qlayer_main<<<blocks, 256>>>((const float4*)x, (float4*)d_out, B);
}